// round 1
// baseline (speedup 1.0000x reference)
#include <cuda_runtime.h>
#include <cstdint>

#define N_NODES 50000
#define NNZ_C   800000
#define K_DIM   256
#define H_DIM   128
#define LN_EPS  1e-5f

// ---------------------------------------------------------------------------
// Scratch (device globals; allocation inside kernel_launch is forbidden)
// g_h            : s0 = x @ W + b                    [50000,128]
// g_acc[0..2]    : s1, s2, s3 (accumulators)         [50000,128] each
// ---------------------------------------------------------------------------
__device__ float g_h[(size_t)N_NODES * H_DIM];
__device__ float g_acc[3][(size_t)N_NODES * H_DIM];

// ---------------------------------------------------------------------------
// Zero the three accumulators (graph replays require re-zeroing every call)
// ---------------------------------------------------------------------------
__global__ void zero_kernel() {
    const size_t n4 = (size_t)3 * N_NODES * H_DIM / 4;
    float4* p = reinterpret_cast<float4*>(&g_acc[0][0]);
    const float4 z = make_float4(0.f, 0.f, 0.f, 0.f);
    for (size_t i = (size_t)blockIdx.x * blockDim.x + threadIdx.x; i < n4;
         i += (size_t)gridDim.x * blockDim.x)
        p[i] = z;
}

// ---------------------------------------------------------------------------
// GEMM: g_h = X[50000,256] @ W[256,128] + b
// 128x128 block tile, BK=8, 256 threads, 8x8 register tile per thread.
// ---------------------------------------------------------------------------
__global__ __launch_bounds__(256) void gemm_kernel(const float* __restrict__ X,
                                                   const float* __restrict__ W,
                                                   const float* __restrict__ bias) {
    __shared__ float As[8][128];   // [k][row]
    __shared__ float Bs[8][128];   // [k][col]

    const int tid = threadIdx.x;
    const int tx = tid & 15;       // col group (16 groups x 8 cols)
    const int ty = tid >> 4;       // row group (16 groups x 8 rows)
    const int row0 = blockIdx.x * 128;

    // A-tile loader mapping: each thread loads one float4 of X
    const int arow = tid >> 1;            // 0..127
    const int ak   = (tid & 1) * 4;       // 0 or 4
    const int grow = min(row0 + arow, N_NODES - 1);
    // B-tile loader mapping
    const int brow = tid >> 5;            // 0..7
    const int bcol = (tid & 31) * 4;      // 0..124

    float acc[8][8];
#pragma unroll
    for (int i = 0; i < 8; i++)
#pragma unroll
        for (int j = 0; j < 8; j++) acc[i][j] = 0.f;

    for (int k0 = 0; k0 < K_DIM; k0 += 8) {
        const float4 av = *reinterpret_cast<const float4*>(
            X + (size_t)grow * K_DIM + k0 + ak);
        const float4 bv = *reinterpret_cast<const float4*>(
            W + (size_t)(k0 + brow) * H_DIM + bcol);
        __syncthreads();
        As[ak + 0][arow] = av.x;
        As[ak + 1][arow] = av.y;
        As[ak + 2][arow] = av.z;
        As[ak + 3][arow] = av.w;
        *reinterpret_cast<float4*>(&Bs[brow][bcol]) = bv;
        __syncthreads();

#pragma unroll
        for (int kk = 0; kk < 8; kk++) {
            float a[8], b[8];
            const float4 a0 = *reinterpret_cast<const float4*>(&As[kk][ty * 8]);
            const float4 a1 = *reinterpret_cast<const float4*>(&As[kk][ty * 8 + 4]);
            const float4 b0 = *reinterpret_cast<const float4*>(&Bs[kk][tx * 8]);
            const float4 b1 = *reinterpret_cast<const float4*>(&Bs[kk][tx * 8 + 4]);
            a[0]=a0.x; a[1]=a0.y; a[2]=a0.z; a[3]=a0.w;
            a[4]=a1.x; a[5]=a1.y; a[6]=a1.z; a[7]=a1.w;
            b[0]=b0.x; b[1]=b0.y; b[2]=b0.z; b[3]=b0.w;
            b[4]=b1.x; b[5]=b1.y; b[6]=b1.z; b[7]=b1.w;
#pragma unroll
            for (int i = 0; i < 8; i++)
#pragma unroll
                for (int j = 0; j < 8; j++) acc[i][j] += a[i] * b[j];
        }
    }

    // epilogue: add bias, store to g_h
    const int colb = tx * 8;
    const float4 bia0 = *reinterpret_cast<const float4*>(bias + colb);
    const float4 bia1 = *reinterpret_cast<const float4*>(bias + colb + 4);
#pragma unroll
    for (int i = 0; i < 8; i++) {
        const int row = row0 + ty * 8 + i;
        if (row < N_NODES) {
            float4 o0, o1;
            o0.x = acc[i][0] + bia0.x; o0.y = acc[i][1] + bia0.y;
            o0.z = acc[i][2] + bia0.z; o0.w = acc[i][3] + bia0.w;
            o1.x = acc[i][4] + bia1.x; o1.y = acc[i][5] + bia1.y;
            o1.z = acc[i][6] + bia1.z; o1.w = acc[i][7] + bia1.w;
            float* op = g_h + (size_t)row * H_DIM + colb;
            *reinterpret_cast<float4*>(op)     = o0;
            *reinterpret_cast<float4*>(op + 4) = o1;
        }
    }
}

// ---------------------------------------------------------------------------
// SpMM (COO): dst[row] += val * src[col], one warp per edge, float4 per lane.
// src_id/dst_id: 0 -> g_h, 1..3 -> g_acc[id-1]. Adjacency selector is read
// from device memory (idxp) so no host readback is needed.
// ---------------------------------------------------------------------------
__device__ __forceinline__ float* state_ptr(int id) {
    return (id == 0) ? g_h : g_acc[id - 1];
}

__global__ __launch_bounds__(256) void spmm_kernel(const int*   __restrict__ rows_base,
                                                   const int*   __restrict__ cols_base,
                                                   const float* __restrict__ vals_base,
                                                   const int*   __restrict__ idxp,
                                                   int src_id, int dst_id) {
    const int si = __ldg(idxp);
    const size_t off = (size_t)si * NNZ_C;
    const int*   rows = rows_base + off;
    const int*   cols = cols_base + off;
    const float* vals = vals_base + off;
    const float* __restrict__ src = state_ptr(src_id);
    float*       __restrict__ dst = state_ptr(dst_id);

    const int lane   = threadIdx.x & 31;
    const int warp   = (blockIdx.x * blockDim.x + threadIdx.x) >> 5;
    const int nwarps = (gridDim.x * blockDim.x) >> 5;

    for (int e = warp; e < NNZ_C; e += nwarps) {
        const int   row = __ldg(rows + e);
        const int   col = __ldg(cols + e);
        const float val = __ldg(vals + e);
        const float4 xv = __ldg(reinterpret_cast<const float4*>(
                                    src + (size_t)col * H_DIM) + lane);
        float* p = dst + (size_t)row * H_DIM + lane * 4;
        asm volatile("red.global.add.v4.f32 [%0], {%1, %2, %3, %4};"
                     :: "l"(p), "f"(xv.x * val), "f"(xv.y * val),
                        "f"(xv.z * val), "f"(xv.w * val)
                     : "memory");
    }
}

// ---------------------------------------------------------------------------
// LayerNorm (population var) + exact-erf GELU. One warp per row.
// ---------------------------------------------------------------------------
__global__ __launch_bounds__(256) void ln_gelu_kernel(const float* __restrict__ gamma,
                                                      const float* __restrict__ beta,
                                                      float* __restrict__ out) {
    const int warp = (blockIdx.x * blockDim.x + threadIdx.x) >> 5;
    const int lane = threadIdx.x & 31;
    if (warp >= N_NODES) return;

    const float* yrow = g_acc[2] + (size_t)warp * H_DIM;
    const float4 v = *reinterpret_cast<const float4*>(yrow + lane * 4);

    float s  = v.x + v.y + v.z + v.w;
    float sq = v.x * v.x + v.y * v.y + v.z * v.z + v.w * v.w;
#pragma unroll
    for (int o = 16; o; o >>= 1) {
        s  += __shfl_xor_sync(0xFFFFFFFFu, s,  o);
        sq += __shfl_xor_sync(0xFFFFFFFFu, sq, o);
    }
    const float mean = s * (1.f / H_DIM);
    const float var  = sq * (1.f / H_DIM) - mean * mean;
    const float rstd = rsqrtf(var + LN_EPS);

    const float4 g = *reinterpret_cast<const float4*>(gamma + lane * 4);
    const float4 b = *reinterpret_cast<const float4*>(beta  + lane * 4);

    auto gelu = [](float t) {
        return 0.5f * t * (1.f + erff(t * 0.7071067811865476f));
    };
    float4 r;
    r.x = gelu((v.x - mean) * rstd * g.x + b.x);
    r.y = gelu((v.y - mean) * rstd * g.y + b.y);
    r.z = gelu((v.z - mean) * rstd * g.z + b.z);
    r.w = gelu((v.w - mean) * rstd * g.w + b.w);

    *reinterpret_cast<float4*>(out + (size_t)warp * H_DIM + lane * 4) = r;
}

// ---------------------------------------------------------------------------
// kernel_launch
// inputs (metadata order): x, adj_rows, adj_cols, adj_vals, idxes_seq,
//                          idxes_res, W, b, gamma, beta
// ---------------------------------------------------------------------------
extern "C" void kernel_launch(void* const* d_in, const int* in_sizes, int n_in,
                              void* d_out, int out_size) {
    const float* x        = (const float*)d_in[0];
    const int*   adj_rows = (const int*)  d_in[1];
    const int*   adj_cols = (const int*)  d_in[2];
    const float* adj_vals = (const float*)d_in[3];
    const int*   idx_seq  = (const int*)  d_in[4];
    const int*   idx_res  = (const int*)  d_in[5];
    const float* W        = (const float*)d_in[6];
    const float* b        = (const float*)d_in[7];
    const float* gamma    = (const float*)d_in[8];
    const float* beta     = (const float*)d_in[9];
    float*       out      = (float*)d_out;

    zero_kernel<<<1024, 256>>>();
    gemm_kernel<<<(N_NODES + 127) / 128, 256>>>(x, W, b);

    const int SPMM_BLOCKS = 2048;
    // state ids: 0 = s0 (g_h), 1 = s1, 2 = s2, 3 = s3
    // step 0: s1  = A[seq0] @ s0
    spmm_kernel<<<SPMM_BLOCKS, 256>>>(adj_rows, adj_cols, adj_vals, idx_seq + 0, 0, 1);
    // step 1: s2  = A[seq1] @ s1 + A[res0] @ s0
    spmm_kernel<<<SPMM_BLOCKS, 256>>>(adj_rows, adj_cols, adj_vals, idx_seq + 1, 1, 2);
    spmm_kernel<<<SPMM_BLOCKS, 256>>>(adj_rows, adj_cols, adj_vals, idx_res + 0, 0, 2);
    // step 2: s3  = A[seq2] @ s2 + A[res1] @ s0 + A[res2] @ s1
    spmm_kernel<<<SPMM_BLOCKS, 256>>>(adj_rows, adj_cols, adj_vals, idx_seq + 2, 2, 3);
    spmm_kernel<<<SPMM_BLOCKS, 256>>>(adj_rows, adj_cols, adj_vals, idx_res + 1, 0, 3);
    spmm_kernel<<<SPMM_BLOCKS, 256>>>(adj_rows, adj_cols, adj_vals, idx_res + 2, 1, 3);

    ln_gelu_kernel<<<(N_NODES * 32 + 255) / 256, 256>>>(gamma, beta, out);
}